// round 7
// baseline (speedup 1.0000x reference)
#include <cuda_runtime.h>
#include <stdint.h>

// Instant-NGP hash-grid interpolation encoding.
// B=262144 points, DIM=3, L=16 levels, T=19 (2^19-entry tables), F=2 features.
//
// Model (validated R1-R5): L1tex lane-wavefront bound (~1 gathered line /SM/cyc).
// Avg lane-loads/thread = 6: even g0 (p=1/2) -> both x-corners in one aligned
// float4 (4 loads); odd g0 -> 8.
//
// R6: branchless. Per combo: unconditional Q1 = tab4[u>>1]; predicated
// Q2 = tab4[v>>1] only when m != 1 (single-statement if -> @P LDG, no BSSY).
// For m==1, v = u^1 lives in Q1. Removes warp-divergence serialization and
// lets all 8 load sites issue back-to-back (full MLP).

#define NB   262144
#define NL   16
#define TBITS 19
#define TMASK ((1u << TBITS) - 1u)

__constant__ float c_res[NL] = {
    16.f, 20.f, 25.f, 32.f, 40.f, 50.f, 64.f, 80.f,
    101.f, 128.f, 161.f, 203.f, 256.f, 322.f, 406.f, 512.f
};

__global__ void __launch_bounds__(256)
ngp_interp_kernel(const float* __restrict__ x,
                  const float2* __restrict__ tables,
                  float2* __restrict__ out)
{
    const int tid = blockIdx.x * 256 + threadIdx.x;   // tid = b*16 + l
    const int l = tid & (NL - 1);
    const int b = tid >> 4;

    const float res = c_res[l];

    const float x0 = __ldg(x + b * 3 + 0);
    const float x1 = __ldg(x + b * 3 + 1);
    const float x2 = __ldg(x + b * 3 + 2);

    const float s0 = x0 * res, s1 = x1 * res, s2 = x2 * res;
    const float g0f = floorf(s0), g1f = floorf(s1), g2f = floorf(s2);
    const float f0 = s0 - g0f, f1 = s1 - g1f, f2 = s2 - g2f;

    const unsigned g0 = (unsigned)g0f;
    const unsigned g1 = (unsigned)g1f;
    const unsigned g2 = (unsigned)g2f;

    const unsigned P1 = 2654435761u, P2 = 805459861u;

    const unsigned h1a = g1 * P1, h1b = (g1 + 1u) * P1;
    const unsigned h2a = g2 * P2, h2b = (g2 + 1u) * P2;

    const float4* __restrict__ tab4 =
        (const float4*)(tables + ((size_t)l << TBITS));

    const float w0a = 1.f - f0, w0b = f0;
    const float w1a = 1.f - f1, w1b = f1;
    const float w2a = 1.f - f2, w2b = f2;

    unsigned hy[4];
    hy[0] = h1a ^ h2a;  hy[1] = h1b ^ h2a;
    hy[2] = h1a ^ h2b;  hy[3] = h1b ^ h2b;

    float wp[4];
    wp[0] = w1a * w2a;  wp[1] = w1b * w2a;
    wp[2] = w1a * w2b;  wp[3] = w1b * w2b;

    // Corner index pair per combo: u = g0^hy (weight w0a), v = u^m (weight w0b).
    const unsigned m = g0 ^ (g0 + 1u);
    const bool needQ2 = (m != 1u);

    unsigned u[4], v[4];
#pragma unroll
    for (int p = 0; p < 4; p++) {
        u[p] = (g0 ^ hy[p]) & TMASK;
        v[p] = u[p] ^ (m & TMASK);
    }

    // Unconditional loads: float4 containing u (and also v when m==1).
    float4 Q1[4];
#pragma unroll
    for (int p = 0; p < 4; p++) Q1[p] = __ldg(tab4 + (u[p] >> 1));

    // Predicated loads: float4 containing v, only when it's a different one.
    float4 Q2[4];
#pragma unroll
    for (int p = 0; p < 4; p++) Q2[p] = Q1[p];
#pragma unroll
    for (int p = 0; p < 4; p++) {
        if (needQ2) Q2[p] = __ldg(tab4 + (v[p] >> 1));
    }

    float a0 = 0.f, a1 = 0.f;
#pragma unroll
    for (int p = 0; p < 4; p++) {
        const bool hiU = (u[p] & 1u) != 0u;
        const bool hiV = (v[p] & 1u) != 0u;
        const float vux = hiU ? Q1[p].z : Q1[p].x;
        const float vuy = hiU ? Q1[p].w : Q1[p].y;
        const float vvx = hiV ? Q2[p].z : Q2[p].x;
        const float vvy = hiV ? Q2[p].w : Q2[p].y;
        const float wU = w0a * wp[p];
        const float wV = w0b * wp[p];
        a0 += wU * vux + wV * vvx;
        a1 += wU * vuy + wV * vvy;
    }

    out[tid] = make_float2(a0, a1);   // out[b,l]: fully coalesced
}

extern "C" void kernel_launch(void* const* d_in, const int* in_sizes, int n_in,
                              void* d_out, int out_size)
{
    const float* x   = (const float*)d_in[0];
    const float* tab = (const float*)d_in[1];
    if (n_in >= 2 && in_sizes[0] > in_sizes[1]) {
        const float* t = x; x = tab; tab = t;
    }

    const int total = NB * NL;
    ngp_interp_kernel<<<total / 256, 256>>>(x, (const float2*)tab, (float2*)d_out);
}